// round 9
// baseline (speedup 1.0000x reference)
#include <cuda_runtime.h>

// ============================================================================
// Flash attention (fp32, packed f32x2 FMA) for B=4,H=8,S=2048,D=64 + key mask.
//   scores = (Q K^T)/8 + (1-mask)*(-1e30);  out = softmax(scores) V
// One CTA = 64 query rows x full KV loop (32 tiles of 64 keys).
// 128 threads: tx = tid&15 (16 key/dim columns of 4), ty = tid>>4 (8 rows of 8).
// All MMA work uses fma.rn.f32x2 (2 fp32 MACs per issue on the fma pipe).
// ============================================================================

#define S_LEN   2048
#define HDIM    64
#define BM      64
#define BN      64
#define NTILES  (S_LEN / BN)
#define BATCH   4
#define HEADS   8

// shared memory layout (floats)
#define QOFF 0                       // Qs[d][64]   (transposed, swizzled)
#define KOFF (QOFF + 64 * 64)        // Kd[d][128]  (transposed, value-duplicated pairs, swizzled)
#define VOFF (KOFF + 64 * 128)       // Vs[n][64]   (natural)
#define POFF (VOFF + 64 * 64)        // Pd[k][128]  (transposed P, duplicated pairs, swizzled)
#define MOFF (POFF + 64 * 128)       // maskadd[64]
#define SMEM_FLOATS (MOFF + 64)
#define SMEM_BYTES  (SMEM_FLOATS * 4)

// ---------------------------------------------------------------- f32x2 ops
__device__ __forceinline__ unsigned long long fma2(unsigned long long a,
                                                   unsigned long long b,
                                                   unsigned long long c) {
    unsigned long long d;
    asm("fma.rn.f32x2 %0, %1, %2, %3;" : "=l"(d) : "l"(a), "l"(b), "l"(c));
    return d;
}
__device__ __forceinline__ unsigned long long mul2(unsigned long long a,
                                                   unsigned long long b) {
    unsigned long long d;
    asm("mul.rn.f32x2 %0, %1, %2;" : "=l"(d) : "l"(a), "l"(b));
    return d;
}
__device__ __forceinline__ unsigned long long pack2(float x, float y) {
    unsigned long long r;
    asm("mov.b64 %0, {%1, %2};" : "=l"(r)
        : "r"(__float_as_uint(x)), "r"(__float_as_uint(y)));
    return r;
}
__device__ __forceinline__ float2 unpack2(unsigned long long v) {
    unsigned int lo, hi;
    asm("mov.b64 {%0, %1}, %2;" : "=r"(lo), "=r"(hi) : "l"(v));
    return make_float2(__uint_as_float(lo), __uint_as_float(hi));
}

__global__ void __launch_bounds__(128, 2)
fa_f32x2_kernel(const float* __restrict__ Q, const float* __restrict__ K,
                const float* __restrict__ V, const int* __restrict__ mask,
                float* __restrict__ out) {
    extern __shared__ float sm[];
    float* sq  = sm + QOFF;
    float* sk  = sm + KOFF;
    float* sv  = sm + VOFF;
    float* sp  = sm + POFF;
    float* sma = sm + MOFF;

    const int tid = threadIdx.x;
    const int tx  = tid & 15;   // 0..15
    const int ty  = tid >> 4;   // 0..7
    const int bh  = blockIdx.y;             // 0..31
    const int b   = bh >> 3;
    const int m0  = blockIdx.x * BM;
    const size_t base = (size_t)bh * S_LEN * HDIM;

    // ---- load Q tile: transpose to [d][m] with x0.125 scale, granule-XOR swizzle
    {
        const float* qg = Q + base + (size_t)m0 * HDIM;
#pragma unroll
        for (int r = 0; r < 8; r++) {
            int idx = tid + r * 128;
            int m = idx >> 4, dg = idx & 15;
            float4 v = *(const float4*)(qg + m * HDIM + dg * 4);
            float vv[4] = {v.x * 0.125f, v.y * 0.125f, v.z * 0.125f, v.w * 0.125f};
#pragma unroll
            for (int k = 0; k < 4; k++) {
                // element (d=4dg+k, m): granule (m>>2) ^ (d>>2)
                sq[(4 * dg + k) * 64 + (((m >> 2) ^ dg) << 2) + (m & 3)] = vv[k];
            }
        }
    }

    unsigned long long oacc[8][2];
    float mrow[8], lrow[8];
#pragma unroll
    for (int i = 0; i < 8; i++) {
        oacc[i][0] = 0ull; oacc[i][1] = 0ull;
        mrow[i] = __int_as_float(0xff800000);  // -inf
        lrow[i] = 0.f;
    }

    for (int t = 0; t < NTILES; t++) {
        const int n0 = t * BN;
        __syncthreads();  // prev tile's PV done reading sv/sp, S done reading sk

        // ---- K tile: transpose to [d][2n] value-duplicated pairs, swizzled
        {
            const float* kg = K + base + (size_t)n0 * HDIM;
#pragma unroll
            for (int r = 0; r < 8; r++) {
                int idx = tid + r * 128;
                int n = idx >> 4, dg = idx & 15;
                float4 v = *(const float4*)(kg + n * HDIM + dg * 4);
                float vv[4] = {v.x, v.y, v.z, v.w};
#pragma unroll
                for (int k = 0; k < 4; k++) {
                    int d  = 4 * dg + k;
                    int gp = (n >> 1) ^ (d & 31);
                    *(float2*)(sk + d * 128 + (gp << 2) + 2 * (n & 1)) =
                        make_float2(vv[k], vv[k]);
                }
            }
        }
        // ---- V tile: natural [n][d] copy
        {
            const float* vg = V + base + (size_t)n0 * HDIM;
#pragma unroll
            for (int r = 0; r < 8; r++) {
                int idx = tid + r * 128;
                int n = idx >> 4, dg = idx & 15;
                *(float4*)(sv + n * 64 + dg * 4) =
                    *(const float4*)(vg + n * HDIM + dg * 4);
            }
        }
        // ---- mask additive term for this key tile
        if (tid < 64) {
            sma[tid] = (1.0f - (float)mask[b * S_LEN + n0 + tid]) * (-1e30f);
        }
        __syncthreads();

        // ================= S = Q K^T (rows packed in pairs) =================
        unsigned long long sacc[4][4];
#pragma unroll
        for (int ip = 0; ip < 4; ip++)
#pragma unroll
            for (int j = 0; j < 4; j++) sacc[ip][j] = 0ull;

#pragma unroll 4
        for (int d = 0; d < 64; d++) {
            const int kq = (d >> 2) & 15;
            const ulonglong2 qa =
                *(const ulonglong2*)(sq + d * 64 + ((((ty << 1) | 0) ^ kq) << 2));
            const ulonglong2 qb =
                *(const ulonglong2*)(sq + d * 64 + ((((ty << 1) | 1) ^ kq) << 2));
            const int kk = d & 31;
            const ulonglong2 ka =
                *(const ulonglong2*)(sk + d * 128 + ((((tx << 1) | 0) ^ kk) << 2));
            const ulonglong2 kb =
                *(const ulonglong2*)(sk + d * 128 + ((((tx << 1) | 1) ^ kk) << 2));
            unsigned long long qp[4] = {qa.x, qa.y, qb.x, qb.y};  // row pairs
            unsigned long long kd[4] = {ka.x, ka.y, kb.x, kb.y};  // dup'd cols
#pragma unroll
            for (int ip = 0; ip < 4; ip++)
#pragma unroll
                for (int j = 0; j < 4; j++)
                    sacc[ip][j] = fma2(qp[ip], kd[j], sacc[ip][j]);
        }

        // ================= online softmax =================
        float madd[4];
#pragma unroll
        for (int j = 0; j < 4; j++) madd[j] = sma[tx * 4 + j];

        float p[8][4];
#pragma unroll
        for (int ip = 0; ip < 4; ip++)
#pragma unroll
            for (int j = 0; j < 4; j++) {
                float2 f = unpack2(sacc[ip][j]);
                p[2 * ip][j]     = f.x + madd[j];
                p[2 * ip + 1][j] = f.y + madd[j];
            }

#pragma unroll
        for (int i = 0; i < 8; i++) {
            float mx = fmaxf(fmaxf(p[i][0], p[i][1]), fmaxf(p[i][2], p[i][3]));
#pragma unroll
            for (int o = 1; o < 16; o <<= 1)
                mx = fmaxf(mx, __shfl_xor_sync(0xffffffffu, mx, o));
            const float mnew  = fmaxf(mrow[i], mx);
            const float alpha = __expf(mrow[i] - mnew);
            mrow[i] = mnew;
            float rs = 0.f;
#pragma unroll
            for (int j = 0; j < 4; j++) {
                p[i][j] = __expf(p[i][j] - mnew);
                rs += p[i][j];
            }
#pragma unroll
            for (int o = 1; o < 16; o <<= 1)
                rs += __shfl_xor_sync(0xffffffffu, rs, o);
            lrow[i] = lrow[i] * alpha + rs;
            const unsigned long long a2 = pack2(alpha, alpha);
            oacc[i][0] = mul2(oacc[i][0], a2);
            oacc[i][1] = mul2(oacc[i][1], a2);
        }

        // ---- write P transposed + duplicated: Pd[k][2m,2m+1] = p
#pragma unroll
        for (int j = 0; j < 4; j++) {
            const int krow = tx * 4 + j;
            const int key  = krow & 31;
            float* prow = sp + krow * 128;
#pragma unroll
            for (int ip = 0; ip < 4; ip++) {
                const int gp = (ty * 4 + ip) ^ key;
                *(float4*)(prow + (gp << 2)) =
                    make_float4(p[2 * ip][j], p[2 * ip][j],
                                p[2 * ip + 1][j], p[2 * ip + 1][j]);
            }
        }
        __syncthreads();

        // ================= O += P V (cols packed in pairs) =================
#pragma unroll 4
        for (int k2 = 0; k2 < 64; k2++) {
            const int key = k2 & 31;
            const float* prow = sp + k2 * 128;
            const ulonglong2 pa =
                *(const ulonglong2*)(prow + (((ty * 4 + 0) ^ key) << 2));
            const ulonglong2 pb =
                *(const ulonglong2*)(prow + (((ty * 4 + 1) ^ key) << 2));
            const ulonglong2 pc =
                *(const ulonglong2*)(prow + (((ty * 4 + 2) ^ key) << 2));
            const ulonglong2 pd =
                *(const ulonglong2*)(prow + (((ty * 4 + 3) ^ key) << 2));
            unsigned long long pr[8] = {pa.x, pa.y, pb.x, pb.y,
                                        pc.x, pc.y, pd.x, pd.y};
            const ulonglong2 vv = *(const ulonglong2*)(sv + k2 * 64 + (tx << 2));
#pragma unroll
            for (int i = 0; i < 8; i++) {
                oacc[i][0] = fma2(pr[i], vv.x, oacc[i][0]);
                oacc[i][1] = fma2(pr[i], vv.y, oacc[i][1]);
            }
        }
    }

    // ================= epilogue: O / l =================
    float* og = out + base + (size_t)m0 * HDIM;
#pragma unroll
    for (int i = 0; i < 8; i++) {
        const float inv = 1.0f / lrow[i];
        float2 a = unpack2(oacc[i][0]);
        float2 c = unpack2(oacc[i][1]);
        *(float4*)(og + (ty * 8 + i) * HDIM + tx * 4) =
            make_float4(a.x * inv, a.y * inv, c.x * inv, c.y * inv);
    }
}

extern "C" void kernel_launch(void* const* d_in, const int* in_sizes, int n_in,
                              void* d_out, int out_size) {
    const float* Q   = (const float*)d_in[0];
    const float* K   = (const float*)d_in[1];
    const float* V   = (const float*)d_in[2];
    const int*  mask = (const int*)d_in[3];
    float* out = (float*)d_out;

    cudaFuncSetAttribute(fa_f32x2_kernel,
                         cudaFuncAttributeMaxDynamicSharedMemorySize, SMEM_BYTES);

    dim3 grid(S_LEN / BM, BATCH * HEADS);  // 32 x 32 = 1024 CTAs
    fa_f32x2_kernel<<<grid, 128, SMEM_BYTES>>>(Q, K, V, mask, out);
}

// round 10
// speedup vs baseline: 1.0024x; 1.0024x over previous
#include <cuda_runtime.h>

// ============================================================================
// Flash attention (fp32, packed f32x2 FMA) for B=4,H=8,S=2048,D=64 + key mask.
//   scores = (Q K^T)/8 + (1-mask)*(-1e30);  out = softmax(scores) V
// One CTA = 64 query rows x full KV loop (32 tiles of 64 keys).
// 128 threads: tx = tid&15 (16 key/dim columns of 4), ty = tid>>4 (8 rows of 8).
// All MMA work uses fma.rn.f32x2 (2 fp32 MACs per issue on the fma pipe).
// ============================================================================

#define S_LEN   2048
#define HDIM    64
#define BM      64
#define BN      64
#define NTILES  (S_LEN / BN)
#define BATCH   4
#define HEADS   8

// shared memory layout (floats)
#define QOFF 0                       // Qs[d][64]   (transposed, swizzled)
#define KOFF (QOFF + 64 * 64)        // Kd[d][128]  (transposed, value-duplicated pairs, swizzled)
#define VOFF (KOFF + 64 * 128)       // Vs[n][64]   (natural)
#define POFF (VOFF + 64 * 64)        // Pd[k][128]  (transposed P, duplicated pairs, swizzled)
#define MOFF (POFF + 64 * 128)       // maskadd[64]
#define SMEM_FLOATS (MOFF + 64)
#define SMEM_BYTES  (SMEM_FLOATS * 4)

// ---------------------------------------------------------------- f32x2 ops
__device__ __forceinline__ unsigned long long fma2(unsigned long long a,
                                                   unsigned long long b,
                                                   unsigned long long c) {
    unsigned long long d;
    asm("fma.rn.f32x2 %0, %1, %2, %3;" : "=l"(d) : "l"(a), "l"(b), "l"(c));
    return d;
}
__device__ __forceinline__ unsigned long long mul2(unsigned long long a,
                                                   unsigned long long b) {
    unsigned long long d;
    asm("mul.rn.f32x2 %0, %1, %2;" : "=l"(d) : "l"(a), "l"(b));
    return d;
}
__device__ __forceinline__ unsigned long long pack2(float x, float y) {
    unsigned long long r;
    asm("mov.b64 %0, {%1, %2};" : "=l"(r)
        : "r"(__float_as_uint(x)), "r"(__float_as_uint(y)));
    return r;
}
__device__ __forceinline__ float2 unpack2(unsigned long long v) {
    unsigned int lo, hi;
    asm("mov.b64 {%0, %1}, %2;" : "=r"(lo), "=r"(hi) : "l"(v));
    return make_float2(__uint_as_float(lo), __uint_as_float(hi));
}

__global__ void __launch_bounds__(128, 2)
fa_f32x2_kernel(const float* __restrict__ Q, const float* __restrict__ K,
                const float* __restrict__ V, const int* __restrict__ mask,
                float* __restrict__ out) {
    extern __shared__ float sm[];
    float* sq  = sm + QOFF;
    float* sk  = sm + KOFF;
    float* sv  = sm + VOFF;
    float* sp  = sm + POFF;
    float* sma = sm + MOFF;

    const int tid = threadIdx.x;
    const int tx  = tid & 15;   // 0..15
    const int ty  = tid >> 4;   // 0..7
    const int bh  = blockIdx.y;             // 0..31
    const int b   = bh >> 3;
    const int m0  = blockIdx.x * BM;
    const size_t base = (size_t)bh * S_LEN * HDIM;

    // ---- load Q tile: transpose to [d][m] with x0.125 scale, granule-XOR swizzle
    {
        const float* qg = Q + base + (size_t)m0 * HDIM;
#pragma unroll
        for (int r = 0; r < 8; r++) {
            int idx = tid + r * 128;
            int m = idx >> 4, dg = idx & 15;
            float4 v = *(const float4*)(qg + m * HDIM + dg * 4);
            float vv[4] = {v.x * 0.125f, v.y * 0.125f, v.z * 0.125f, v.w * 0.125f};
#pragma unroll
            for (int k = 0; k < 4; k++) {
                // element (d=4dg+k, m): granule (m>>2) ^ (d>>2)
                sq[(4 * dg + k) * 64 + (((m >> 2) ^ dg) << 2) + (m & 3)] = vv[k];
            }
        }
    }

    unsigned long long oacc[8][2];
    float mrow[8], lrow[8];
#pragma unroll
    for (int i = 0; i < 8; i++) {
        oacc[i][0] = 0ull; oacc[i][1] = 0ull;
        mrow[i] = __int_as_float(0xff800000);  // -inf
        lrow[i] = 0.f;
    }

    for (int t = 0; t < NTILES; t++) {
        const int n0 = t * BN;
        __syncthreads();  // prev tile's PV done reading sv/sp, S done reading sk

        // ---- K tile: transpose to [d][2n] value-duplicated pairs, swizzled
        {
            const float* kg = K + base + (size_t)n0 * HDIM;
#pragma unroll
            for (int r = 0; r < 8; r++) {
                int idx = tid + r * 128;
                int n = idx >> 4, dg = idx & 15;
                float4 v = *(const float4*)(kg + n * HDIM + dg * 4);
                float vv[4] = {v.x, v.y, v.z, v.w};
#pragma unroll
                for (int k = 0; k < 4; k++) {
                    int d  = 4 * dg + k;
                    int gp = (n >> 1) ^ (d & 31);
                    *(float2*)(sk + d * 128 + (gp << 2) + 2 * (n & 1)) =
                        make_float2(vv[k], vv[k]);
                }
            }
        }
        // ---- V tile: natural [n][d] copy
        {
            const float* vg = V + base + (size_t)n0 * HDIM;
#pragma unroll
            for (int r = 0; r < 8; r++) {
                int idx = tid + r * 128;
                int n = idx >> 4, dg = idx & 15;
                *(float4*)(sv + n * 64 + dg * 4) =
                    *(const float4*)(vg + n * HDIM + dg * 4);
            }
        }
        // ---- mask additive term for this key tile
        if (tid < 64) {
            sma[tid] = (1.0f - (float)mask[b * S_LEN + n0 + tid]) * (-1e30f);
        }
        __syncthreads();

        // ================= S = Q K^T (rows packed in pairs) =================
        unsigned long long sacc[4][4];
#pragma unroll
        for (int ip = 0; ip < 4; ip++)
#pragma unroll
            for (int j = 0; j < 4; j++) sacc[ip][j] = 0ull;

#pragma unroll 4
        for (int d = 0; d < 64; d++) {
            const int kq = (d >> 2) & 15;
            const ulonglong2 qa =
                *(const ulonglong2*)(sq + d * 64 + ((((ty << 1) | 0) ^ kq) << 2));
            const ulonglong2 qb =
                *(const ulonglong2*)(sq + d * 64 + ((((ty << 1) | 1) ^ kq) << 2));
            const int kk = d & 31;
            const ulonglong2 ka =
                *(const ulonglong2*)(sk + d * 128 + ((((tx << 1) | 0) ^ kk) << 2));
            const ulonglong2 kb =
                *(const ulonglong2*)(sk + d * 128 + ((((tx << 1) | 1) ^ kk) << 2));
            unsigned long long qp[4] = {qa.x, qa.y, qb.x, qb.y};  // row pairs
            unsigned long long kd[4] = {ka.x, ka.y, kb.x, kb.y};  // dup'd cols
#pragma unroll
            for (int ip = 0; ip < 4; ip++)
#pragma unroll
                for (int j = 0; j < 4; j++)
                    sacc[ip][j] = fma2(qp[ip], kd[j], sacc[ip][j]);
        }

        // ================= online softmax =================
        float madd[4];
#pragma unroll
        for (int j = 0; j < 4; j++) madd[j] = sma[tx * 4 + j];

        float p[8][4];
#pragma unroll
        for (int ip = 0; ip < 4; ip++)
#pragma unroll
            for (int j = 0; j < 4; j++) {
                float2 f = unpack2(sacc[ip][j]);
                p[2 * ip][j]     = f.x + madd[j];
                p[2 * ip + 1][j] = f.y + madd[j];
            }

#pragma unroll
        for (int i = 0; i < 8; i++) {
            float mx = fmaxf(fmaxf(p[i][0], p[i][1]), fmaxf(p[i][2], p[i][3]));
#pragma unroll
            for (int o = 1; o < 16; o <<= 1)
                mx = fmaxf(mx, __shfl_xor_sync(0xffffffffu, mx, o));
            const float mnew  = fmaxf(mrow[i], mx);
            const float alpha = __expf(mrow[i] - mnew);
            mrow[i] = mnew;
            float rs = 0.f;
#pragma unroll
            for (int j = 0; j < 4; j++) {
                p[i][j] = __expf(p[i][j] - mnew);
                rs += p[i][j];
            }
#pragma unroll
            for (int o = 1; o < 16; o <<= 1)
                rs += __shfl_xor_sync(0xffffffffu, rs, o);
            lrow[i] = lrow[i] * alpha + rs;
            const unsigned long long a2 = pack2(alpha, alpha);
            oacc[i][0] = mul2(oacc[i][0], a2);
            oacc[i][1] = mul2(oacc[i][1], a2);
        }

        // ---- write P transposed + duplicated: Pd[k][2m,2m+1] = p
#pragma unroll
        for (int j = 0; j < 4; j++) {
            const int krow = tx * 4 + j;
            const int key  = krow & 31;
            float* prow = sp + krow * 128;
#pragma unroll
            for (int ip = 0; ip < 4; ip++) {
                const int gp = (ty * 4 + ip) ^ key;
                *(float4*)(prow + (gp << 2)) =
                    make_float4(p[2 * ip][j], p[2 * ip][j],
                                p[2 * ip + 1][j], p[2 * ip + 1][j]);
            }
        }
        __syncthreads();

        // ================= O += P V (cols packed in pairs) =================
#pragma unroll 4
        for (int k2 = 0; k2 < 64; k2++) {
            const int key = k2 & 31;
            const float* prow = sp + k2 * 128;
            const ulonglong2 pa =
                *(const ulonglong2*)(prow + (((ty * 4 + 0) ^ key) << 2));
            const ulonglong2 pb =
                *(const ulonglong2*)(prow + (((ty * 4 + 1) ^ key) << 2));
            const ulonglong2 pc =
                *(const ulonglong2*)(prow + (((ty * 4 + 2) ^ key) << 2));
            const ulonglong2 pd =
                *(const ulonglong2*)(prow + (((ty * 4 + 3) ^ key) << 2));
            unsigned long long pr[8] = {pa.x, pa.y, pb.x, pb.y,
                                        pc.x, pc.y, pd.x, pd.y};
            const ulonglong2 vv = *(const ulonglong2*)(sv + k2 * 64 + (tx << 2));
#pragma unroll
            for (int i = 0; i < 8; i++) {
                oacc[i][0] = fma2(pr[i], vv.x, oacc[i][0]);
                oacc[i][1] = fma2(pr[i], vv.y, oacc[i][1]);
            }
        }
    }

    // ================= epilogue: O / l =================
    float* og = out + base + (size_t)m0 * HDIM;
#pragma unroll
    for (int i = 0; i < 8; i++) {
        const float inv = 1.0f / lrow[i];
        float2 a = unpack2(oacc[i][0]);
        float2 c = unpack2(oacc[i][1]);
        *(float4*)(og + (ty * 8 + i) * HDIM + tx * 4) =
            make_float4(a.x * inv, a.y * inv, c.x * inv, c.y * inv);
    }
}

extern "C" void kernel_launch(void* const* d_in, const int* in_sizes, int n_in,
                              void* d_out, int out_size) {
    const float* Q   = (const float*)d_in[0];
    const float* K   = (const float*)d_in[1];
    const float* V   = (const float*)d_in[2];
    const int*  mask = (const int*)d_in[3];
    float* out = (float*)d_out;

    cudaFuncSetAttribute(fa_f32x2_kernel,
                         cudaFuncAttributeMaxDynamicSharedMemorySize, SMEM_BYTES);

    dim3 grid(S_LEN / BM, BATCH * HEADS);  // 32 x 32 = 1024 CTAs
    fa_f32x2_kernel<<<grid, 128, SMEM_BYTES>>>(Q, K, V, mask, out);
}